// round 15
// baseline (speedup 1.0000x reference)
#include <cuda_runtime.h>
#include <math.h>
#include <stdint.h>

#define BATCH 16
#define LROWS 192   // 6*L rows
#define AC    2046  // attributor columns
#define MC    2048  // nodes
#define LD    32    // L
#define SLABF (8 * AC)        // 16368 floats per 8-row slab
#define SLABB (SLABF * 4)     // 65472 bytes
#define DYNB  (2 * SLABB)     // 130944 bytes dynamic smem (attr slab + W1 slab)

// Scratch (device globals; zero-initialized at load, no allocation)
__device__ float g_hp[BATCH][16][2][MC];   // h partials: g<8 -> hq, g>=8 -> hk (m=0/2047 never written, stay 0)
__device__ float g_causal[BATCH][2][MC];   // causal columns, [n][m]
__device__ float g_S[BATCH][2][64];        // S (complete per j, from V blocks)
__device__ int   g_c1[BATCH];              // K1 finisher counters (self-resetting)
__device__ int   g_c2[BATCH];              // K3 finisher counters

__device__ __forceinline__ unsigned smem_u32(const void* p) {
    unsigned a;
    asm("{ .reg .u64 t; cvta.to.shared.u64 t, %1; cvt.u32.u64 %0, t; }"
        : "=r"(a) : "l"(p));
    return a;
}
__device__ __forceinline__ void mbar_init(unsigned a, unsigned cnt) {
    asm volatile("mbarrier.init.shared.b64 [%0], %1;" :: "r"(a), "r"(cnt) : "memory");
}
__device__ __forceinline__ void mbar_expect(unsigned a, unsigned tx) {
    asm volatile("mbarrier.arrive.expect_tx.shared.b64 _, [%0], %1;"
                 :: "r"(a), "r"(tx) : "memory");
}
__device__ __forceinline__ void bulk_g2s(unsigned dst, const float* src,
                                         unsigned bytes, unsigned mbar) {
    asm volatile(
        "cp.async.bulk.shared::cluster.global.mbarrier::complete_tx::bytes "
        "[%0], [%1], %2, [%3];"
        :: "r"(dst), "l"(src), "r"(bytes), "r"(mbar) : "memory");
}
__device__ __forceinline__ void mbar_wait(unsigned a, unsigned par) {
    asm volatile(
        "{\n\t.reg .pred P;\n"
        "W%=:\n\t"
        "mbarrier.try_wait.parity.acquire.cta.shared::cta.b64 P, [%0], %1, 0x989680;\n\t"
        "@P bra D%=;\n\t"
        "bra W%=;\n"
        "D%=:\n\t}"
        :: "r"(a), "r"(par) : "memory");
}

// ---------------------------------------------------------------------------
// K1: Q/K streaming via bulk-copied row slabs. grid (g=16, b=16), 512 thr.
// g<8: Q rows 8g..8g+7; g>=8: K rows. Slab (attr + W1) bulk-loaded to smem;
// wq/wk folds computed under the copy latency. Thread owns 4 columns,
// accumulates h partials over its 8 rows -> g_hp. Last block of each batch
// reduces partials, adds special-node h, computes causal -> g_causal.
// ---------------------------------------------------------------------------
__global__ __launch_bounds__(512) void qk_kernel(
    const float* __restrict__ user, const float* __restrict__ item,
    const float* __restrict__ attr, const float* __restrict__ W1,
    const float* __restrict__ W2,
    const float* __restrict__ adj, const float* __restrict__ iw) {

    extern __shared__ __align__(16) float dyn[];    // [A slab | W slab]
    __shared__ float usit[2 * LROWS];
    __shared__ float qsks[2][2][32];
    __shared__ float wqs[2][64], wks[2][64];
    __shared__ uint64_t mbar;
    __shared__ int fin;

    int g = blockIdx.x, b = blockIdx.y, t = threadIdx.x;
    int qk = g >> 3;
    unsigned mb = smem_u32(&mbar);

    if (t == 0) mbar_init(mb, 1);
    if (t < LROWS)            usit[t] = user[b * LROWS + t];
    else if (t < 2 * LROWS)   usit[t] = item[b * LROWS + (t - LROWS)];
    __syncthreads();

    if (t == 0) {
        asm volatile("fence.proxy.async.shared::cta;" ::: "memory");
        mbar_expect(mb, DYNB);
        const float* srcA = attr + ((size_t)b * LROWS + 8 * g) * AC;
        const float* srcW = W1 + (size_t)(8 * g) * AC;
        unsigned dA = smem_u32(dyn), dW = smem_u32(dyn + SLABF);
        #pragma unroll
        for (int i = 0; i < 4; i++) {
            bulk_g2s(dA + (unsigned)i * 16368u, srcA + (size_t)i * 2 * AC, 16368u, mb);
            bulk_g2s(dW + (unsigned)i * 16368u, srcW + (size_t)i * 2 * AC, 16368u, mb);
        }
    }

    // folds overlap the bulk copy
    if (t < 128) {
        int n = t >> 6, q = (t >> 5) & 1, l = t & 31;
        float s = 0.f;
        if (q == 0) {
            #pragma unroll
            for (int j = 0; j < 64; j++)
                s = fmaf(fmaxf(usit[n * LROWS + j], 0.f), W2[j * LD + l], s);
            qsks[n][0][l] = s;
        } else {
            #pragma unroll
            for (int j = 0; j < 64; j++)
                s = fmaf(fmaxf(usit[n * LROWS + 64 + j], 0.f), W2[(64 + j) * LD + l], s);
            qsks[n][1][l] = s;
        }
    }
    __syncthreads();
    if (t < 256) {
        int n = t >> 7, sel = (t >> 6) & 1, j = t & 63;
        float s = 0.f;
        if (sel == 0) {
            #pragma unroll
            for (int l = 0; l < 32; l++) s = fmaf(W2[j * LD + l], qsks[n][1][l], s);
            wqs[n][j] = s;
        } else {
            #pragma unroll
            for (int l = 0; l < 32; l++) s = fmaf(W2[(64 + j) * LD + l], qsks[n][0][l], s);
            wks[n][j] = s;
        }
    }
    __syncthreads();

    mbar_wait(mb, 0);

    // compute h partials over this slab
    {
        const float (*wsel)[64] = qk ? wks : wqs;
        const float* A = dyn;
        const float* W = dyn + SLABF;
        int j0 = 8 * (g & 7);
        #pragma unroll
        for (int k = 0; k < 4; k++) {
            int c = t + 512 * k;
            if (c < AC) {
                float a0 = 0.f, a1 = 0.f;
                #pragma unroll
                for (int r = 0; r < 8; r++) {
                    float x = fmaxf(A[r * AC + c] * W[r * AC + c], 0.f);
                    a0 = fmaf(x, wsel[0][j0 + r], a0);
                    a1 = fmaf(x, wsel[1][j0 + r], a1);
                }
                g_hp[b][g][0][c + 1] = a0;
                g_hp[b][g][1][c + 1] = a1;
            }
        }
    }
    __threadfence();
    __syncthreads();

    if (t == 0) {
        int v = atomicAdd(&g_c1[b], 1);
        fin = (v == 15);
        if (v == 15) g_c1[b] = 0;    // reset for next launch
    }
    __syncthreads();
    if (!fin) return;

    // ---- finisher: reduce partials, specials, causal ----
    float* hq = dyn;          // [n*2048 + m], aliases dead slab
    float* hk = dyn + 4096;
    #pragma unroll
    for (int k = 0; k < 4; k++) {
        int m = t + 512 * k;
        float q0 = 0.f, q1 = 0.f, k0 = 0.f, k1 = 0.f;
        #pragma unroll
        for (int g2 = 0; g2 < 8; g2++) {
            q0 += __ldcg(&g_hp[b][g2][0][m]);
            q1 += __ldcg(&g_hp[b][g2][1][m]);
            k0 += __ldcg(&g_hp[b][g2 + 8][0][m]);
            k1 += __ldcg(&g_hp[b][g2 + 8][1][m]);
        }
        hq[m] = q0; hq[2048 + m] = q1;
        hk[m] = k0; hk[2048 + m] = k1;
    }
    __syncthreads();
    if (t < 8) {               // special nodes m=0 (user), m=2047 (item)
        int n = t & 1, which = t >> 1;
        float s = 0.f;
        #pragma unroll
        for (int j = 0; j < 64; j++) {
            if (which == 0)      s = fmaf(fmaxf(usit[j], 0.f),             wqs[n][j], s);
            else if (which == 1) s = fmaf(fmaxf(usit[LROWS + j], 0.f),     wqs[n][j], s);
            else if (which == 2) s = fmaf(fmaxf(usit[64 + j], 0.f),        wks[n][j], s);
            else                 s = fmaf(fmaxf(usit[LROWS + 64 + j], 0.f), wks[n][j], s);
        }
        if (which == 0)      hq[n * 2048]        = s;
        else if (which == 1) hq[n * 2048 + 2047] = s;
        else if (which == 2) hk[n * 2048]        = s;
        else                 hk[n * 2048 + 2047] = s;
    }
    __syncthreads();
    #pragma unroll
    for (int k = 0; k < 4; k++) {
        int m = t + 512 * k;
        #pragma unroll
        for (int n = 0; n < 2; n++) {
            int coln = n ? (MC - 1) : 0;
            float aAv = adj[(size_t)m * MC + coln];
            float aPv = aAv * iw[(size_t)m * MC + coln];
            float aRv = adj[(size_t)coln * MC + m] * iw[(size_t)coln * MC + m];
            float d = hq[n * 2048 + m] * aPv - hk[n * 2048 + m] * aRv;
            g_causal[b][n][m] = aAv / (1.f + expf(-d));
        }
    }
}

// ---------------------------------------------------------------------------
// K3: V streaming. grid (vg=8, b=16), 512 thr. Bulk-loads its 8 V rows,
// loads causal[b] into smem, folds x*causal into S[j] (complete over m) via
// warp+block reduction. Last block per batch adds special-node terms and
// projects to out (plain stores).
// ---------------------------------------------------------------------------
__global__ __launch_bounds__(512) void v_kernel(
    const float* __restrict__ user, const float* __restrict__ item,
    const float* __restrict__ attr, const float* __restrict__ W1,
    const float* __restrict__ W2, float* __restrict__ out) {

    extern __shared__ __align__(16) float dyn[];    // [A slab | W slab]
    __shared__ float csh[2 * MC];   // causal [n*2048+m]
    __shared__ float usv[64], itv[64];
    __shared__ float wbuf[16][16];
    __shared__ float Ssum[128];
    __shared__ uint64_t mbar;
    __shared__ int fin;

    int vg = blockIdx.x, b = blockIdx.y, t = threadIdx.x;
    int w = t >> 5, l = t & 31;
    unsigned mb = smem_u32(&mbar);
    int r0 = 128 + 8 * vg;

    if (t == 0) mbar_init(mb, 1);
    __syncthreads();
    if (t == 0) {
        asm volatile("fence.proxy.async.shared::cta;" ::: "memory");
        mbar_expect(mb, DYNB);
        const float* srcA = attr + ((size_t)b * LROWS + r0) * AC;
        const float* srcW = W1 + (size_t)r0 * AC;
        unsigned dA = smem_u32(dyn), dW = smem_u32(dyn + SLABF);
        #pragma unroll
        for (int i = 0; i < 4; i++) {
            bulk_g2s(dA + (unsigned)i * 16368u, srcA + (size_t)i * 2 * AC, 16368u, mb);
            bulk_g2s(dW + (unsigned)i * 16368u, srcW + (size_t)i * 2 * AC, 16368u, mb);
        }
    }
    // load causal + special V rows (overlaps bulk)
    #pragma unroll
    for (int i = 0; i < 8; i++)
        csh[t + 512 * i] = ((const float*)g_causal[b])[t + 512 * i];
    if (t < 64)            usv[t] = user[b * LROWS + 128 + t];
    else if (t < 128)      itv[t - 64] = item[b * LROWS + 128 + (t - 64)];
    __syncthreads();
    mbar_wait(mb, 0);

    // fold V slab into S partials (complete over this block's m range)
    float sj[8][2];
    #pragma unroll
    for (int r = 0; r < 8; r++) { sj[r][0] = 0.f; sj[r][1] = 0.f; }
    {
        const float* A = dyn;
        const float* W = dyn + SLABF;
        #pragma unroll
        for (int k = 0; k < 4; k++) {
            int c = t + 512 * k;
            if (c < AC) {
                float c0v = csh[c + 1], c1v = csh[2048 + c + 1];
                #pragma unroll
                for (int r = 0; r < 8; r++) {
                    float x = fmaxf(A[r * AC + c] * W[r * AC + c], 0.f);
                    sj[r][0] = fmaf(x, c0v, sj[r][0]);
                    sj[r][1] = fmaf(x, c1v, sj[r][1]);
                }
            }
        }
    }
    #pragma unroll
    for (int r = 0; r < 8; r++)
        #pragma unroll
        for (int n = 0; n < 2; n++)
            #pragma unroll
            for (int off = 16; off; off >>= 1)
                sj[r][n] += __shfl_xor_sync(0xffffffffu, sj[r][n], off);
    if (l == 0) {
        #pragma unroll
        for (int r = 0; r < 8; r++) {
            wbuf[w][r * 2]     = sj[r][0];
            wbuf[w][r * 2 + 1] = sj[r][1];
        }
    }
    __syncthreads();
    if (t < 16) {
        float s = 0.f;
        #pragma unroll
        for (int ww = 0; ww < 16; ww++) s += wbuf[ww][t];
        int r = t >> 1, n = t & 1;
        g_S[b][n][8 * vg + r] = s;
        __threadfence();
    }
    __syncthreads();

    if (t == 0) {
        int v = atomicAdd(&g_c2[b], 1);
        fin = (v == 7);
        if (v == 7) g_c2[b] = 0;
    }
    __syncthreads();
    if (!fin) return;

    // ---- finisher: special-node contributions + projection ----
    if (t < 128) {
        int n = t >> 6, j = t & 63;
        float s = __ldcg(&g_S[b][n][j]);
        s = fmaf(fmaxf(usv[j], 0.f), csh[n * 2048],        s);   // m = 0 (user)
        s = fmaf(fmaxf(itv[j], 0.f), csh[n * 2048 + 2047], s);   // m = 2047 (item)
        Ssum[n * 64 + j] = s;
    }
    __syncthreads();
    if (t < 64) {
        int ll = t >> 1, n = t & 1;
        float s = 0.f;
        #pragma unroll
        for (int j = 0; j < 64; j++)
            s = fmaf(W2[(128 + j) * LD + ll], Ssum[n * 64 + j], s);
        out[b * 64 + ll * 2 + n] = s;
    }
}

extern "C" void kernel_launch(void* const* d_in, const int* in_sizes, int n_in,
                              void* d_out, int out_size) {
    const float* user       = (const float*)d_in[0];
    const float* item       = (const float*)d_in[1];
    const float* attributor = (const float*)d_in[2];
    const float* adj        = (const float*)d_in[3];
    const float* iw         = (const float*)d_in[4];
    const float* W1         = (const float*)d_in[5];
    const float* W2         = (const float*)d_in[6];
    float* out = (float*)d_out;

    cudaFuncSetAttribute(qk_kernel, cudaFuncAttributeMaxDynamicSharedMemorySize, DYNB);
    cudaFuncSetAttribute(v_kernel,  cudaFuncAttributeMaxDynamicSharedMemorySize, DYNB);

    qk_kernel<<<dim3(16, BATCH), 512, DYNB>>>(user, item, attributor, W1, W2, adj, iw);
    v_kernel <<<dim3(8,  BATCH), 512, DYNB>>>(user, item, attributor, W1, W2, out);
}

// round 16
// speedup vs baseline: 3.4524x; 3.4524x over previous
#include <cuda_runtime.h>
#include <math.h>

// Problem constants
#define BATCH 16
#define LROWS 192   // 6*L rows of raw
#define AC    2046  // attributor columns
#define MC    2048  // M = A + 2
#define LD    32    // L (W_2 output dim)
#define TM    128   // columns of m per block in main kernel
#define MB    (MC / TM)   // 16 m-blocks

// Scratch (device globals; no allocation allowed)
__device__ float g_wq[BATCH][2][64];   // wq[b][n][j]
__device__ float g_wk[BATCH][2][64];   // wk[b][n][j]
__device__ float g_A[2][MC];           // adj[m][col_n]
__device__ float g_P[2][MC];           // adj[m][col_n] * iw[m][col_n]
__device__ float g_R[2][MC];           // adj[col_n][m] * iw[col_n][m]

// ---------------------------------------------------------------------------
// Kernel 1 (prep): wq/wk folds + adj/iw packing + d_out zeroing.
// grid 48 x 128. W2[0:128] prefetched to smem in parallel with user/item
// loads so the fold phases are LDS-latency, not DRAM-latency.  (R6 verbatim)
// ---------------------------------------------------------------------------
__global__ __launch_bounds__(128) void prep_kernel(
    const float* __restrict__ user, const float* __restrict__ item,
    const float* __restrict__ W2,
    const float* __restrict__ adj, const float* __restrict__ iw,
    float* __restrict__ out) {

    int blk = blockIdx.x;
    int t = threadIdx.x;

    if (blk < 32) {
        int b = blk >> 1;
        int n = blk & 1;
        const float* src = (n ? item : user) + b * LROWS;
        __shared__ float W2s[128 * 33];   // padded rows: conflict-free both ways
        __shared__ float xr[128];
        __shared__ float qs[32];
        __shared__ float ks[32];

        xr[t] = fmaxf(src[t], 0.0f);
        #pragma unroll
        for (int i = 0; i < 32; i++) {
            int idx = t + i * 128;            // 0..4095
            W2s[(idx >> 5) * 33 + (idx & 31)] = W2[idx];
        }
        __syncthreads();

        if (t < 32) {
            float s = 0.0f;
            #pragma unroll
            for (int j = 0; j < 64; j++) s = fmaf(xr[j], W2s[j * 33 + t], s);
            qs[t] = s;
        } else if (t < 64) {
            int l = t - 32;
            float s = 0.0f;
            #pragma unroll
            for (int j = 0; j < 64; j++) s = fmaf(xr[64 + j], W2s[(64 + j) * 33 + l], s);
            ks[l] = s;
        }
        __syncthreads();
        if (t < 64) {
            float swq = 0.0f, swk = 0.0f;
            #pragma unroll
            for (int l = 0; l < 32; l++) {
                swq = fmaf(W2s[t * 33 + l],        ks[l], swq);
                swk = fmaf(W2s[(64 + t) * 33 + l], qs[l], swk);
            }
            g_wq[b][n][t] = swq;
            g_wk[b][n][t] = swk;
        }
    } else {
        if (blk == 32) {          // zero d_out (1024 floats) for the atomics
            float4 z = make_float4(0.f, 0.f, 0.f, 0.f);
            ((float4*)out)[t]       = z;
            ((float4*)out)[t + 128] = z;
        }
        int m = (blk - 32) * 128 + t;
        size_t row = (size_t)m * MC;
        float a0 = adj[row];
        float a1 = adj[row + (MC - 1)];
        g_A[0][m] = a0;
        g_A[1][m] = a1;
        g_P[0][m] = a0 * iw[row];
        g_P[1][m] = a1 * iw[row + (MC - 1)];
        g_R[0][m] = adj[m] * iw[m];
        size_t lastrow = (size_t)(MC - 1) * MC + m;
        g_R[1][m] = adj[lastrow] * iw[lastrow];
    }
}

// ---------------------------------------------------------------------------
// Kernel 2 (main): R6 streaming pass + fused projection epilogue, launched
// with PDL. Prologue issues all prep-independent loads (W2e + the first
// 8+8 av/wv chunk) BEFORE cudaGridDependencySynchronize(), so prep's
// execution hides under main's launch + first-chunk DRAM latency.
// grid (mb=16, b=16), 384 threads.
// ---------------------------------------------------------------------------
__global__ __launch_bounds__(384) void main_kernel(
    const float* __restrict__ user, const float* __restrict__ item,
    const float* __restrict__ attributor, const float* __restrict__ W1,
    const float* __restrict__ W2, float* __restrict__ out) {

    __shared__ float Vsh[64][TM + 1];
    __shared__ float hq_sh[2][TM];
    __shared__ float hk_sh[2][TM];
    __shared__ float c_sh[2][TM];
    __shared__ float wq_sh[2][64];
    __shared__ float wk_sh[2][64];
    __shared__ float W2e[64][LD];    // W2 rows 128..191 (value projection)
    __shared__ float Ssh[2 * 64];    // partial S for this block

    int b  = blockIdx.y;
    int mb = blockIdx.x;
    int t  = threadIdx.x;
    int group = t >> 7;          // 0,1,2
    int ml = t & (TM - 1);
    int m  = mb * TM + ml;

    bool isU = (m == 0), isI = (m == MC - 1);
    bool special = isU || isI;
    int mm1 = special ? 0 : (m - 1);    // safe offset (never deref OOB)
    const float* ap = attributor + ((size_t)b * LROWS + group * 64) * AC + mm1;
    const float* wp = W1 + (size_t)(group * 64) * AC + mm1;

    // ---- prep-independent prologue: W2e staging + first av/wv chunk ----
    if (t >= 128) {
        int r = t - 128;                       // 0..255, 8 floats each
        ((float4*)W2e)[r]       = ((const float4*)(W2 + 128 * LD))[r];
        ((float4*)W2e)[r + 256] = ((const float4*)(W2 + 128 * LD))[r + 256];
    }
    float av0[8], wv0[8];
    if (!special) {
        #pragma unroll
        for (int u = 0; u < 8; u++) av0[u] = ap[(size_t)u * AC];
        #pragma unroll
        for (int u = 0; u < 8; u++) wv0[u] = wp[(size_t)u * AC];
    }

    // ---- wait for prep (PDL); then consume its outputs ----
    cudaGridDependencySynchronize();
    if (t < 128) {
        ((float*)wq_sh)[t] = ((const float*)g_wq[b])[t];
        ((float*)wk_sh)[t] = ((const float*)g_wk[b])[t];
    }
    __syncthreads();

    if (group < 2) {
        const float (*wsel)[64] = (group == 0) ? wq_sh : wk_sh;
        float h0 = 0.0f, h1 = 0.0f;
        if (special) {
            const float* up = (isU ? user : item) + b * LROWS + group * 64;
            #pragma unroll
            for (int j = 0; j < 64; j++) {
                float x = fmaxf(up[j], 0.0f);
                h0 = fmaf(x, wsel[0][j], h0);
                h1 = fmaf(x, wsel[1][j], h1);
            }
        } else {
            // chunk 0 from the prefetched registers
            #pragma unroll
            for (int u = 0; u < 8; u++) {
                float x = fmaxf(av0[u] * wv0[u], 0.0f);
                h0 = fmaf(x, wsel[0][u], h0);
                h1 = fmaf(x, wsel[1][u], h1);
            }
            #pragma unroll 2
            for (int jb = 8; jb < 64; jb += 8) {
                float av[8], wv[8];
                #pragma unroll
                for (int u = 0; u < 8; u++) av[u] = ap[(size_t)(jb + u) * AC];
                #pragma unroll
                for (int u = 0; u < 8; u++) wv[u] = wp[(size_t)(jb + u) * AC];
                #pragma unroll
                for (int u = 0; u < 8; u++) {
                    float x = fmaxf(av[u] * wv[u], 0.0f);
                    h0 = fmaf(x, wsel[0][jb + u], h0);
                    h1 = fmaf(x, wsel[1][jb + u], h1);
                }
            }
        }
        if (group == 0) { hq_sh[0][ml] = h0; hq_sh[1][ml] = h1; }
        else            { hk_sh[0][ml] = h0; hk_sh[1][ml] = h1; }
    } else {
        if (special) {
            const float* up = (isU ? user : item) + b * LROWS + 128;
            #pragma unroll
            for (int j = 0; j < 64; j++) Vsh[j][ml] = fmaxf(up[j], 0.0f);
        } else {
            // chunk 0 from the prefetched registers
            #pragma unroll
            for (int u = 0; u < 8; u++)
                Vsh[u][ml] = fmaxf(av0[u] * wv0[u], 0.0f);
            #pragma unroll 2
            for (int jb = 8; jb < 64; jb += 8) {
                float av[8], wv[8];
                #pragma unroll
                for (int u = 0; u < 8; u++) av[u] = ap[(size_t)(jb + u) * AC];
                #pragma unroll
                for (int u = 0; u < 8; u++) wv[u] = wp[(size_t)(jb + u) * AC];
                #pragma unroll
                for (int u = 0; u < 8; u++)
                    Vsh[jb + u][ml] = fmaxf(av[u] * wv[u], 0.0f);
            }
        }
    }
    __syncthreads();

    // causal[b, m, col_n] = sigmoid(h[m,n] - h[n,m]) * adj[m, col_n]
    if (t < 256) {
        int n  = t >> 7;
        int mm = t & (TM - 1);
        int mg = mb * TM + mm;
        float d = hq_sh[n][mm] * g_P[n][mg] - hk_sh[n][mm] * g_R[n][mg];
        c_sh[n][mm] = g_A[n][mg] / (1.0f + expf(-d));
    }
    __syncthreads();

    // partial S[n][j] = sum_mm Vsh[j][mm] * c_sh[n][mm]
    if (t < 128) {
        int n = t >> 6;
        int j = t & 63;
        float s = 0.0f;
        #pragma unroll 8
        for (int mm = 0; mm < TM; mm++)
            s = fmaf(Vsh[j][mm], c_sh[n][mm], s);
        Ssh[t] = s;
    }
    __syncthreads();

    // fused projection: out[b,l,n] += sum_j W2e[j][l] * S[n][j]
    if (t < 64) {
        int l = t >> 1;
        int n = t & 1;
        float s = 0.0f;
        #pragma unroll
        for (int j = 0; j < 64; j++)
            s = fmaf(W2e[j][l], Ssh[n * 64 + j], s);
        atomicAdd(&out[b * 64 + l * 2 + n], s);
    }
}

extern "C" void kernel_launch(void* const* d_in, const int* in_sizes, int n_in,
                              void* d_out, int out_size) {
    const float* user       = (const float*)d_in[0];
    const float* item       = (const float*)d_in[1];
    const float* attributor = (const float*)d_in[2];
    const float* adj        = (const float*)d_in[3];
    const float* iw         = (const float*)d_in[4];
    const float* W1         = (const float*)d_in[5];
    const float* W2         = (const float*)d_in[6];
    float* out = (float*)d_out;

    prep_kernel<<<48, 128>>>(user, item, W2, adj, iw, out);

    // PDL launch: main may begin while prep is still running; main gates its
    // consumption of prep outputs with cudaGridDependencySynchronize().
    cudaLaunchConfig_t cfg = {};
    cfg.gridDim  = dim3(MB, BATCH);
    cfg.blockDim = dim3(384);
    cfg.dynamicSmemBytes = 0;
    cfg.stream = 0;
    cudaLaunchAttribute attrs[1];
    attrs[0].id = cudaLaunchAttributeProgrammaticStreamSerialization;
    attrs[0].val.programmaticStreamSerializationAllowed = 1;
    cfg.attrs = attrs;
    cfg.numAttrs = 1;
    cudaLaunchKernelEx(&cfg, main_kernel, user, item, attributor, W1, W2, out);
}